// round 4
// baseline (speedup 1.0000x reference)
#include <cuda_runtime.h>
#include <cuda_bf16.h>
#include <math.h>

// ---------------- scratch (device globals: allocation-free rule) -------------
__device__ float g_feat[512 * 8192];   // chain output features
__device__ float g_h1[512 * 4096];     // MLP hidden 1
__device__ float g_h2[512 * 4096];     // MLP hidden 2

// Pre-split fragment buffers for the chain:
// B-frag-major (per 64x64 matrix): 32 tiles (kt0..3 x nt0..7) * 32 lanes,
//   each lane one uint4 = {h_reg0, h_reg1, l_reg0, l_reg1}.
__device__ uint4 g_xb[512 * 7 * 2 * 1024];   // x layers 1..7, components r,i  (117MB)
__device__ uint4 g_wb[8 * 2 * 1024];         // W layers 0..7, components r,i
// A-frag-major for x[:,0]^T: 16 tiles (mt,kt) * 32 lanes * {h uint4, l uint4}
__device__ uint4 g_xa[512 * 2 * 1024];       // (16MB)

__device__ __forceinline__ float mishf(float x) {
    float sp = (x > 20.f) ? x : log1pf(expf(x));
    return x * tanhf(sp);
}

__device__ __forceinline__ void mma_m16n8k16(float c[4], const unsigned a[4], const unsigned b[2]) {
    asm volatile(
        "mma.sync.aligned.m16n8k16.row.col.f32.bf16.bf16.f32 "
        "{%0,%1,%2,%3}, {%4,%5,%6,%7}, {%8,%9}, {%0,%1,%2,%3};\n"
        : "+f"(c[0]), "+f"(c[1]), "+f"(c[2]), "+f"(c[3])
        : "r"(a[0]), "r"(a[1]), "r"(a[2]), "r"(a[3]), "r"(b[0]), "r"(b[1]));
}

// pack two fp32 into bf16x2: low half = lo, high half = hi
__device__ __forceinline__ unsigned pack_bf16x2(float lo, float hi) {
    unsigned r;
    asm("cvt.rn.bf16x2.f32 %0, %1, %2;" : "=r"(r) : "f"(hi), "f"(lo));
    return r;
}
__device__ __forceinline__ float2 unpack_bf16x2(unsigned u) {
    __nv_bfloat162 t = *reinterpret_cast<__nv_bfloat162*>(&u);
    return make_float2(__bfloat162float(t.x), __bfloat162float(t.y));
}
// split pair (v0,v1) into hi bf16x2 and lo (residual) bf16x2
__device__ __forceinline__ void split_pair(float v0, float v1, unsigned& h, unsigned& l) {
    h = pack_bf16x2(v0, v1);
    float2 hf = unpack_bf16x2(h);
    l = pack_bf16x2(v0 - hf.x, v1 - hf.y);
}
__device__ __forceinline__ void split2(float v, __nv_bfloat16& h, __nv_bfloat16& l) {
    h = __float2bfloat16_rn(v);
    l = __float2bfloat16_rn(v - __bfloat162float(h));
}

// ---------------------------------------------------------------------------
// Prep: split + transpose all static chain operands into fragment-major bf16.
// mode 0 (B-frag): out[idx], idx = tile*32+lane; tile=(kt*8+nt)
//   values B[k][n] = M[n][k] (B = M^T): v0=M[n][k0] v1=M[n][k0+1] v2=[k0+8] v3=[k0+9]
// mode 1 (A-frag for x0^T): idx = tile*64 + lane*2 + hl; tile=(mt*4+kt)
// ---------------------------------------------------------------------------
__global__ void __launch_bounds__(256)
prep_kernel(const float* __restrict__ x_r, const float* __restrict__ x_i,
            const float* __restrict__ W_r, const float* __restrict__ W_i)
{
    __shared__ float sm[4096];
    const int bid = blockIdx.x, tid = threadIdx.x;
    const float* src;
    uint4* dst;
    int mode;
    if (bid < 7168) {                       // x layers 1..7, B-frag
        int b = bid / 14, rem = bid % 14;
        int l = rem >> 1, c = rem & 1;
        src = (c ? x_i : x_r) + (size_t)b * 8 * 4096 + (size_t)(l + 1) * 4096;
        dst = g_xb + ((size_t)(b * 7 + l) * 2 + c) * 1024;
        mode = 0;
    } else if (bid < 8192) {                // x layer 0, A-frag
        int t = bid - 7168;
        int b = t >> 1, c = t & 1;
        src = (c ? x_i : x_r) + (size_t)b * 8 * 4096;
        dst = g_xa + ((size_t)b * 2 + c) * 1024;
        mode = 1;
    } else {                                // W layers, B-frag
        int t = bid - 8192;
        int w = t >> 1, c = t & 1;
        src = (c ? W_i : W_r) + (size_t)w * 4096;
        dst = g_wb + ((size_t)w * 2 + c) * 1024;
        mode = 0;
    }

    for (int i = tid; i < 4096; i += 256) sm[i] = src[i];
    __syncthreads();

    if (mode == 0) {
        for (int idx = tid; idx < 1024; idx += 256) {
            int tile = idx >> 5, lane = idx & 31;
            int kt = tile >> 3, nt = tile & 7;
            int g = lane >> 2, t = lane & 3;
            int n = 8 * nt + g, k0 = 16 * kt + 2 * t;
            float v0 = sm[n * 64 + k0],     v1 = sm[n * 64 + k0 + 1];
            float v2 = sm[n * 64 + k0 + 8], v3 = sm[n * 64 + k0 + 9];
            uint4 o;
            split_pair(v0, v1, o.x, o.z);
            split_pair(v2, v3, o.y, o.w);
            dst[idx] = o;
        }
    } else {
        for (int idx = tid; idx < 1024; idx += 256) {
            int hl = idx & 1, lane = (idx >> 1) & 31, tile = idx >> 6;
            int mt = tile >> 2, kt = tile & 3;
            int g = lane >> 2, t = lane & 3;
            int r = 16 * mt + g, k0 = 16 * kt + 2 * t;
            // A[r][k] = x0^T[r][k] = x0[k][r]
            float e0 = sm[k0 * 64 + r],           e1 = sm[(k0 + 1) * 64 + r];
            float e2 = sm[k0 * 64 + r + 8],       e3 = sm[(k0 + 1) * 64 + r + 8];
            float e4 = sm[(k0 + 8) * 64 + r],     e5 = sm[(k0 + 9) * 64 + r];
            float e6 = sm[(k0 + 8) * 64 + r + 8], e7 = sm[(k0 + 9) * 64 + r + 8];
            unsigned h0, l0, h1, l1, h2, l2, h3, l3;
            split_pair(e0, e1, h0, l0);
            split_pair(e2, e3, h1, l1);
            split_pair(e4, e5, h2, l2);
            split_pair(e6, e7, h3, l3);
            uint4 o;
            if (hl == 0) { o.x = h0; o.y = h1; o.z = h2; o.w = h3; }
            else         { o.x = l0; o.y = l1; o.z = l2; o.w = l3; }
            dst[idx] = o;
        }
    }
}

// ---------------------------------------------------------------------------
// Phase 1: register-resident chain. CTA = 128 thr (4 warps) per batch b.
// Warp w owns rows 16w..16w+15 of the TRANSPOSED running matrix cur^T.
// Step: D = A @ B, A = cur^T (registers), B = M^T (pre-split global frags).
// D fragments re-pack directly into next step's A fragments (per-thread).
// ---------------------------------------------------------------------------
__global__ void __launch_bounds__(128)
chain_tc2(const float* __restrict__ u_r, const float* __restrict__ u_i,
          float* __restrict__ feat)
{
    const int b = blockIdx.x;
    const int tid = threadIdx.x, lane = tid & 31, warp = tid >> 5;

    unsigned arh[4][4], arl[4][4], aih[4][4], ail[4][4];

    // load initial A = x0^T fragments
    {
        const uint4* pr = g_xa + (size_t)b * 2048;        // c=0 (real)
        const uint4* pi = pr + 1024;                      // c=1 (imag)
        #pragma unroll
        for (int kt = 0; kt < 4; kt++) {
            int o = ((warp * 4 + kt) * 32 + lane) * 2;
            uint4 h = __ldg(&pr[o]);
            uint4 l = __ldg(&pr[o + 1]);
            arh[kt][0] = h.x; arh[kt][1] = h.y; arh[kt][2] = h.z; arh[kt][3] = h.w;
            arl[kt][0] = l.x; arl[kt][1] = l.y; arl[kt][2] = l.z; arl[kt][3] = l.w;
            h = __ldg(&pi[o]);
            l = __ldg(&pi[o + 1]);
            aih[kt][0] = h.x; aih[kt][1] = h.y; aih[kt][2] = h.z; aih[kt][3] = h.w;
            ail[kt][0] = l.x; ail[kt][1] = l.y; ail[kt][2] = l.z; ail[kt][3] = l.w;
        }
    }

    float Dr[8][4], Di[8][4];

    #pragma unroll 1
    for (int s = 0; s < 15; s++) {
        const uint4 *br_base, *bi_base;
        if (s & 1) {
            int l = (s - 1) >> 1;   // x layer l+1
            br_base = g_xb + ((size_t)(b * 7 + l) * 2) * 1024;
        } else {
            br_base = g_wb + (size_t)(s >> 1) * 2048;
        }
        bi_base = br_base + 1024;

        #pragma unroll
        for (int nt = 0; nt < 8; nt++)
            #pragma unroll
            for (int v = 0; v < 4; v++) { Dr[nt][v] = 0.f; Di[nt][v] = 0.f; }

        #pragma unroll
        for (int kt = 0; kt < 4; kt++) {
            unsigned naih[4], nail[4];
            #pragma unroll
            for (int j = 0; j < 4; j++) {
                naih[j] = aih[kt][j] ^ 0x80008000u;
                nail[j] = ail[kt][j] ^ 0x80008000u;
            }
            #pragma unroll
            for (int nt = 0; nt < 8; nt++) {
                int o = (kt * 8 + nt) * 32 + lane;
                uint4 u1 = __ldg(&br_base[o]);    // Mr^T frags (h,h,l,l)
                uint4 u2 = __ldg(&bi_base[o]);    // Mi^T frags
                unsigned brh[2] = {u1.x, u1.y}, brl[2] = {u1.z, u1.w};
                unsigned bih[2] = {u2.x, u2.y}, bil[2] = {u2.z, u2.w};
                // Dr = Ar*Br - Ai*Bi ; Di = Ar*Bi + Ai*Br   (bf16x3 each)
                mma_m16n8k16(Dr[nt], arh[kt], brh);
                mma_m16n8k16(Dr[nt], arh[kt], brl);
                mma_m16n8k16(Dr[nt], arl[kt], brh);
                mma_m16n8k16(Dr[nt], naih,    bih);
                mma_m16n8k16(Dr[nt], naih,    bil);
                mma_m16n8k16(Dr[nt], nail,    bih);
                mma_m16n8k16(Di[nt], aih[kt], brh);
                mma_m16n8k16(Di[nt], aih[kt], brl);
                mma_m16n8k16(Di[nt], ail[kt], brh);
                mma_m16n8k16(Di[nt], arh[kt], bih);
                mma_m16n8k16(Di[nt], arh[kt], bil);
                mma_m16n8k16(Di[nt], arl[kt], bih);
            }
        }

        if (s < 14) {
            // D tiles (2kt, 2kt+1) re-pack into A k16-tile kt (registers only)
            #pragma unroll
            for (int kt = 0; kt < 4; kt++) {
                int j0 = 2 * kt, j1 = 2 * kt + 1;
                split_pair(Dr[j0][0], Dr[j0][1], arh[kt][0], arl[kt][0]);
                split_pair(Dr[j0][2], Dr[j0][3], arh[kt][1], arl[kt][1]);
                split_pair(Dr[j1][0], Dr[j1][1], arh[kt][2], arl[kt][2]);
                split_pair(Dr[j1][2], Dr[j1][3], arh[kt][3], arl[kt][3]);
                split_pair(Di[j0][0], Di[j0][1], aih[kt][0], ail[kt][0]);
                split_pair(Di[j0][2], Di[j0][3], aih[kt][1], ail[kt][1]);
                split_pair(Di[j1][0], Di[j1][1], aih[kt][2], ail[kt][2]);
                split_pair(Di[j1][2], Di[j1][3], aih[kt][3], ail[kt][3]);
            }
        }
    }

    // epilogue: D = out^T. feat[b, p*128 + r] = u_r - outR ; +64: u_i - outI
    const float* ur = u_r + (size_t)b * 4096;
    const float* ui = u_i + (size_t)b * 4096;
    float* fb = feat + (size_t)b * 8192;
    const int g = lane >> 2, t = lane & 3;
    const int r0 = 16 * warp + g;
    #pragma unroll
    for (int nt = 0; nt < 8; nt++) {
        int p0 = 8 * nt + 2 * t;
        fb[p0 * 128 + r0]           = ur[p0 * 64 + r0]           - Dr[nt][0];
        fb[(p0 + 1) * 128 + r0]     = ur[(p0 + 1) * 64 + r0]     - Dr[nt][1];
        fb[p0 * 128 + r0 + 8]       = ur[p0 * 64 + r0 + 8]       - Dr[nt][2];
        fb[(p0 + 1) * 128 + r0 + 8] = ur[(p0 + 1) * 64 + r0 + 8] - Dr[nt][3];
        fb[p0 * 128 + 64 + r0]           = ui[p0 * 64 + r0]           - Di[nt][0];
        fb[(p0 + 1) * 128 + 64 + r0]     = ui[(p0 + 1) * 64 + r0]     - Di[nt][1];
        fb[p0 * 128 + 64 + r0 + 8]       = ui[p0 * 64 + r0 + 8]       - Di[nt][2];
        fb[(p0 + 1) * 128 + 64 + r0 + 8] = ui[(p0 + 1) * 64 + r0 + 8] - Di[nt][3];
    }
}

// ---------------------------------------------------------------------------
// Phase 2: tensor-core MLP GEMM with bf16x3 split (unchanged, known-good).
// ---------------------------------------------------------------------------
#define ABLK 264
#define BBLK 136

template <int K>
__global__ void __launch_bounds__(256)
mlp_gemm_tc(const float* __restrict__ A, const float* __restrict__ Bw,
            const float* __restrict__ bias, float* __restrict__ C)
{
    __shared__ __nv_bfloat16 sAh[16 * ABLK], sAl[16 * ABLK];
    __shared__ __nv_bfloat16 sBh[32 * BBLK], sBl[32 * BBLK];

    const int tid = threadIdx.x;
    const int lane = tid & 31, warp = tid >> 5;

    const int lrow = tid >> 1;
    const int kb2  = tid & 1;
    const int lk0  = kb2 << 4;

    const float* Ag = A  + (size_t)(blockIdx.y * 128 + lrow) * K + lk0;
    const float* Bg = Bw + (size_t)(blockIdx.x * 128 + lrow) * K + lk0;

    const int rA  = lrow & 15, mbL = lrow >> 4;
    const int aA0 = (mbL * 2 + kb2) * ABLK + (rA & 7) * 32 + ((rA >> 3) << 1);
    const int nbL = lrow >> 3, ncL = lrow & 7;
    const int aB0 = (nbL * 2 + kb2) * BBLK + ncL * 16;

    int coA[4], ofA[4], coB[4], ofB[4];
    {
        const int rotA = rA & 3, rotB = ncL & 3;
        #pragma unroll
        for (int j = 0; j < 4; j++) {
            int ii = (j + rotA) & 3;
            coA[j] = ii << 2;
            ofA[j] = ((ii & 1) << 4) | ((ii >> 1) << 2);
            ii = (j + rotB) & 3;
            coB[j] = ii << 2;
            ofB[j] = ((ii & 1) << 3) | ((ii >> 1) << 1);
        }
    }

    const int mb0 = (warp >> 1) * 2;
    const int nb0 = (warp & 1) * 8;

    float acc[2][8][4];
    #pragma unroll
    for (int f = 0; f < 2; f++)
        #pragma unroll
        for (int g = 0; g < 8; g++)
            #pragma unroll
            for (int v = 0; v < 4; v++) acc[f][g][v] = 0.f;

    float4 ra[4], rb[4];
    #pragma unroll
    for (int j = 0; j < 4; j++) {
        ra[j] = *(const float4*)&Ag[coA[j]];
        rb[j] = *(const float4*)&Bg[coB[j]];
    }

    #pragma unroll 1
    for (int kb = 0; kb < K; kb += 32) {
        #pragma unroll
        for (int j = 0; j < 4; j++) {
            float v0 = ra[j].x, v1 = ra[j].y, v2 = ra[j].z, v3 = ra[j].w;
            __nv_bfloat16 h0, h1, h2, h3, l0, l1, l2, l3;
            split2(v0, h0, l0); split2(v1, h1, l1); split2(v2, h2, l2); split2(v3, h3, l3);
            __nv_bfloat162 th0; th0.x = h0; th0.y = h1;
            __nv_bfloat162 th1; th1.x = h2; th1.y = h3;
            __nv_bfloat162 tl0; tl0.x = l0; tl0.y = l1;
            __nv_bfloat162 tl1; tl1.x = l2; tl1.y = l3;
            *(__nv_bfloat162*)&sAh[aA0 + ofA[j]]     = th0;
            *(__nv_bfloat162*)&sAh[aA0 + ofA[j] + 8] = th1;
            *(__nv_bfloat162*)&sAl[aA0 + ofA[j]]     = tl0;
            *(__nv_bfloat162*)&sAl[aA0 + ofA[j] + 8] = tl1;

            v0 = rb[j].x; v1 = rb[j].y; v2 = rb[j].z; v3 = rb[j].w;
            split2(v0, h0, l0); split2(v1, h1, l1); split2(v2, h2, l2); split2(v3, h3, l3);
            __nv_bfloat162 uh0; uh0.x = h0; uh0.y = h1;
            __nv_bfloat162 uh1; uh1.x = h2; uh1.y = h3;
            __nv_bfloat162 ul0; ul0.x = l0; ul0.y = l1;
            __nv_bfloat162 ul1; ul1.x = l2; ul1.y = l3;
            *(__nv_bfloat162*)&sBh[aB0 + ofB[j]]     = uh0;
            *(__nv_bfloat162*)&sBh[aB0 + ofB[j] + 4] = uh1;
            *(__nv_bfloat162*)&sBl[aB0 + ofB[j]]     = ul0;
            *(__nv_bfloat162*)&sBl[aB0 + ofB[j] + 4] = ul1;
        }
        __syncthreads();

        if (kb + 32 < K) {
            #pragma unroll
            for (int j = 0; j < 4; j++) {
                ra[j] = *(const float4*)&Ag[kb + 32 + coA[j]];
                rb[j] = *(const float4*)&Bg[kb + 32 + coB[j]];
            }
        }

        #pragma unroll
        for (int kk = 0; kk < 2; kk++) {
            unsigned ah[2][4], al[2][4];
            #pragma unroll
            for (int f = 0; f < 2; f++) {
                int base = ((mb0 + f) * 2 + kk) * ABLK + lane * 8;
                *(uint4*)ah[f] = *(const uint4*)&sAh[base];
                *(uint4*)al[f] = *(const uint4*)&sAl[base];
            }
            #pragma unroll
            for (int g = 0; g < 8; g++) {
                unsigned bh[2], bl[2];
                int base = ((nb0 + g) * 2 + kk) * BBLK + lane * 4;
                *(uint2*)bh = *(const uint2*)&sBh[base];
                *(uint2*)bl = *(const uint2*)&sBl[base];
                #pragma unroll
                for (int f = 0; f < 2; f++) {
                    mma_m16n8k16(acc[f][g], ah[f], bh);
                    mma_m16n8k16(acc[f][g], ah[f], bl);
                    mma_m16n8k16(acc[f][g], al[f], bh);
                }
            }
        }
        __syncthreads();
    }

    const int row0  = blockIdx.y * 128 + (warp >> 1) * 32 + (lane >> 2);
    const int col00 = blockIdx.x * 128 + (warp & 1) * 64 + (lane & 3) * 2;
    #pragma unroll
    for (int f = 0; f < 2; f++) {
        #pragma unroll
        for (int g = 0; g < 8; g++) {
            int c = col00 + g * 8;
            float b0 = __ldg(&bias[c]), b1 = __ldg(&bias[c + 1]);
            #pragma unroll
            for (int h = 0; h < 2; h++) {
                int r = row0 + f * 16 + h * 8;
                float2 o;
                o.x = mishf(acc[f][g][2 * h]     + b0);
                o.y = mishf(acc[f][g][2 * h + 1] + b1);
                *(float2*)&C[(size_t)r * 4096 + c] = o;
            }
        }
    }
}

// ---------------------------------------------------------------------------
// Phase 3: out[b] = h2[b,:] . w3 + b3
// ---------------------------------------------------------------------------
__global__ void final_kernel(const float* __restrict__ H,
                             const float* __restrict__ w3,
                             const float* __restrict__ b3,
                             float* __restrict__ out)
{
    const int b = blockIdx.x;
    const float* h = H + (size_t)b * 4096;
    float s = 0.f;
    for (int i = threadIdx.x; i < 4096; i += 256)
        s = fmaf(h[i], w3[i], s);
    #pragma unroll
    for (int o = 16; o > 0; o >>= 1)
        s += __shfl_down_sync(0xffffffffu, s, o);
    __shared__ float red[8];
    if ((threadIdx.x & 31) == 0) red[threadIdx.x >> 5] = s;
    __syncthreads();
    if (threadIdx.x == 0) {
        float t = 0.f;
        #pragma unroll
        for (int i = 0; i < 8; i++) t += red[i];
        out[b] = t + b3[0];
    }
}

// ---------------------------------------------------------------------------
extern "C" void kernel_launch(void* const* d_in, const int* in_sizes, int n_in,
                              void* d_out, int out_size)
{
    const float* x_r = (const float*)d_in[0];
    const float* x_i = (const float*)d_in[1];
    const float* u_r = (const float*)d_in[2];
    const float* u_i = (const float*)d_in[3];
    const float* W_r = (const float*)d_in[4];
    const float* W_i = (const float*)d_in[5];
    const float* w1  = (const float*)d_in[6];
    const float* b1  = (const float*)d_in[7];
    const float* w2  = (const float*)d_in[8];
    const float* b2  = (const float*)d_in[9];
    const float* w3  = (const float*)d_in[10];
    const float* b3  = (const float*)d_in[11];
    float* out = (float*)d_out;

    float *feat, *h1, *h2;
    cudaGetSymbolAddress((void**)&feat, g_feat);
    cudaGetSymbolAddress((void**)&h1, g_h1);
    cudaGetSymbolAddress((void**)&h2, g_h2);

    prep_kernel<<<8208, 256>>>(x_r, x_i, W_r, W_i);
    chain_tc2<<<512, 128>>>(u_r, u_i, feat);
    mlp_gemm_tc<8192><<<dim3(32, 4), 256>>>(feat, w1, b1, h1);
    mlp_gemm_tc<4096><<<dim3(32, 4), 256>>>(h1, w2, b2, h2);
    final_kernel<<<512, 256>>>(h2, w3, b3, out);
}